// round 13
// baseline (speedup 1.0000x reference)
#include <cuda_runtime.h>
#include <cuda_bf16.h>
#include <math.h>
#include <stdint.h>

// ---------------- problem constants ----------------
#define B_      2
#define S_      2048
#define BS_     (B_*S_)          // 4096 token rows
#define D_      1024
#define H_      16
#define HD_     64
#define HM_     4096
#define V_      32768
#define LG_     8
#define CHUNK_  64
#define NCHUNK_ (S_/CHUNK_)      // 32
#define QEPS_   1.1920929e-07f

typedef __nv_bfloat16 bf16;

// ---------------- static device scratch ----------------
__device__ float g_x   [BS_*D_];
__device__ bf16  g_xn  [BS_*D_];
__device__ float g_proj[BS_*5*D_];
__device__ float g_rq  [BS_*H_];        // per-(row,head) q-rms reciprocal
__device__ float g_u   [BS_*D_];
__device__ float g_a   [BS_*D_];
__device__ bf16  g_y   [BS_*D_];
__device__ bf16  g_hid [BS_*HM_];
__device__ bf16  g_qkv [BS_*3*D_];
__device__ float g_scanP[B_*D_*NCHUNK_];
__device__ float g_scanA[B_*D_*NCHUNK_];
__device__ float g_scanC[B_*D_*NCHUNK_];
__device__ float2 g_ls[BS_*(V_/128)];
__device__ float g_tgtlog[BS_];
__device__ float g_rowloss[BS_];

// bf16 weight mirrors (converted once per launch)
__device__ bf16 w_gdn_in [LG_*5*D_*D_];
__device__ bf16 w_gdn_out[LG_*D_*D_];
__device__ bf16 w_gdn_fc [LG_*HM_*D_];
__device__ bf16 w_gdn_pj [LG_*D_*HM_];
__device__ bf16 w_qkv    [3*D_*D_];
__device__ bf16 w_apj    [D_*D_];
__device__ bf16 w_afc    [HM_*D_];
__device__ bf16 w_ampj   [D_*HM_];
__device__ bf16 w_emb    [(size_t)V_*D_];

// =====================================================================
// helpers
// =====================================================================
__device__ __forceinline__ uint32_t smem_u32(const void* p) {
    uint32_t a;
    asm("{ .reg .u64 t; cvta.to.shared.u64 t, %1; cvt.u32.u64 %0, t; }"
        : "=r"(a) : "l"(p));
    return a;
}
__device__ __forceinline__ uint32_t pack_bf16(float lo, float hi) {
    __nv_bfloat162 h = __floats2bfloat162_rn(lo, hi);
    return *reinterpret_cast<uint32_t*>(&h);
}
__device__ __forceinline__ void cp16(uint32_t dst, const void* src) {
    asm volatile("cp.async.cg.shared.global [%0], [%1], 16;"
                 :: "r"(dst), "l"(src) : "memory");
}
#define CP_COMMIT() asm volatile("cp.async.commit_group;" ::: "memory")
#define CP_WAIT1()  asm volatile("cp.async.wait_group 1;" ::: "memory")

__device__ __forceinline__ void ldsm4(uint32_t r[4], uint32_t addr) {
    asm volatile("ldmatrix.sync.aligned.m8n8.x4.shared.b16 {%0,%1,%2,%3}, [%4];"
                 : "=r"(r[0]), "=r"(r[1]), "=r"(r[2]), "=r"(r[3]) : "r"(addr));
}
__device__ __forceinline__ void ldsm4t(uint32_t r[4], uint32_t addr) {
    asm volatile("ldmatrix.sync.aligned.m8n8.x4.trans.shared.b16 {%0,%1,%2,%3}, [%4];"
                 : "=r"(r[0]), "=r"(r[1]), "=r"(r[2]), "=r"(r[3]) : "r"(addr));
}
__device__ __forceinline__ void mma_bf16(float c[4], const uint32_t a[4],
                                         const uint32_t b[2]) {
    asm volatile(
        "mma.sync.aligned.m16n8k16.row.col.f32.bf16.bf16.f32 "
        "{%0,%1,%2,%3}, {%4,%5,%6,%7}, {%8,%9}, {%0,%1,%2,%3};"
        : "+f"(c[0]), "+f"(c[1]), "+f"(c[2]), "+f"(c[3])
        : "r"(a[0]), "r"(a[1]), "r"(a[2]), "r"(a[3]), "r"(b[0]), "r"(b[1]));
}
// fast transcendentals (MUFU-based, ~1e-7 rel err)
__device__ __forceinline__ float fast_tanh(float x) {
    return 1.f - 2.f / (__expf(2.f * x) + 1.f);
}
__device__ __forceinline__ float fast_sig(float x) {
    return 1.f / (1.f + __expf(-x));
}

// =====================================================================
// bf16 GEMM: C[M,N] = op(alpha * A[M,K] @ W[N,K]^T)
// mode: 0 fp32 overwrite, 1 fp32 accumulate, 2 bf16 silu, 3 bf16 overwrite,
//       4 logsumexp-partial epilogue (LM head + loss fusion)
// =====================================================================
#define TILE_B  16384u
#define STAGE_B 32768u
#define GT_SMEM_BYTES (3*STAGE_B) // 98304

__global__ __launch_bounds__(256, 2)
void gemm_tc(const bf16* __restrict__ A, const bf16* __restrict__ W,
             void* __restrict__ Cv, int M, int N, int K, float alpha, int mode,
             const float* __restrict__ bias, const int* __restrict__ tgt) {
    extern __shared__ char smraw[];
    const uint32_t sb = smem_u32(smraw);
    const int tid  = threadIdx.x;
    const int lane = tid & 31;
    const int wid  = tid >> 5;
    const int wm   = wid & 3;
    const int wn   = wid >> 2;
    const int bm   = blockIdx.y * 128, bn = blockIdx.x * 128;
    const int gid  = lane >> 2;
    const int tig  = lane & 3;

    float acc[2][8][4];
#pragma unroll
    for (int mt = 0; mt < 2; mt++)
#pragma unroll
        for (int nt = 0; nt < 8; nt++)
#pragma unroll
            for (int j = 0; j < 4; j++) acc[mt][nt][j] = 0.f;

    const int nIter = K >> 6;
    const int lrow  = tid >> 3;
    const int lc    = tid & 7;

#define LOAD_STAGE(it, s) do {                                               \
        int k0 = (it) * 64;                                                   \
        uint32_t base = sb + (uint32_t)(s) * STAGE_B;                         \
        _Pragma("unroll")                                                     \
        for (int i = 0; i < 4; i++) {                                         \
            int r = lrow + i * 32;                                            \
            uint32_t sw = (uint32_t)((lc ^ (r & 7)) << 4);                    \
            cp16(base + (uint32_t)r * 128u + sw,                              \
                 A + (size_t)(bm + r) * K + k0 + lc * 8);                     \
            cp16(base + TILE_B + (uint32_t)r * 128u + sw,                     \
                 W + (size_t)(bn + r) * K + k0 + lc * 8);                     \
        }                                                                     \
    } while (0)

    LOAD_STAGE(0, 0); CP_COMMIT();
    LOAD_STAGE(1, 1); CP_COMMIT();

    const int lg  = lane >> 3;
    const int lgi = lane & 7;

    for (int it = 0; it < nIter; it++) {
        CP_WAIT1();
        __syncthreads();
        if (it + 2 < nIter) LOAD_STAGE(it + 2, (it + 2) % 3);
        CP_COMMIT();

        const uint32_t sA = sb + (uint32_t)(it % 3) * STAGE_B;
        const uint32_t sW = sA + TILE_B;

#pragma unroll
        for (int kk = 0; kk < 4; kk++) {
            uint32_t afr[2][4], bfr[8][2];
#pragma unroll
            for (int mt = 0; mt < 2; mt++) {
                int row = wm * 32 + mt * 16 + lgi + (lg & 1) * 8;
                int chunk = kk * 2 + (lg >> 1);
                ldsm4(afr[mt], sA + (uint32_t)row * 128u +
                               (uint32_t)((chunk ^ (row & 7)) << 4));
            }
#pragma unroll
            for (int ntp = 0; ntp < 4; ntp++) {
                int row = wn * 64 + ntp * 16 + lgi + (lg >> 1) * 8;
                int chunk = kk * 2 + (lg & 1);
                uint32_t t4[4];
                ldsm4(t4, sW + (uint32_t)row * 128u +
                          (uint32_t)((chunk ^ (row & 7)) << 4));
                bfr[2 * ntp][0] = t4[0]; bfr[2 * ntp][1] = t4[1];
                bfr[2 * ntp + 1][0] = t4[2]; bfr[2 * ntp + 1][1] = t4[3];
            }
#pragma unroll
            for (int mt = 0; mt < 2; mt++)
#pragma unroll
                for (int nt = 0; nt < 8; nt++)
                    mma_bf16(acc[mt][nt], afr[mt], bfr[nt]);
        }
    }

    if (mode == 4) {
        // ---- fused logsumexp-partial epilogue (LM head) ----
        __syncthreads();
        float2* sm_ls = reinterpret_cast<float2*>(smraw);
#pragma unroll
        for (int mt = 0; mt < 2; mt++) {
            int rA = bm + wm * 32 + mt * 16 + gid;
            int rB = rA + 8;
            float vA[16], vB[16];
            float mA = -1e30f, mB = -1e30f;
#pragma unroll
            for (int nt = 0; nt < 8; nt++) {
                int col = bn + wn * 64 + nt * 8 + tig * 2;
                float2 bv = *reinterpret_cast<const float2*>(bias + col);
                vA[2 * nt]     = acc[mt][nt][0] + bv.x;
                vA[2 * nt + 1] = acc[mt][nt][1] + bv.y;
                vB[2 * nt]     = acc[mt][nt][2] + bv.x;
                vB[2 * nt + 1] = acc[mt][nt][3] + bv.y;
                mA = fmaxf(mA, fmaxf(vA[2 * nt], vA[2 * nt + 1]));
                mB = fmaxf(mB, fmaxf(vB[2 * nt], vB[2 * nt + 1]));
            }
#pragma unroll
            for (int o = 1; o <= 2; o <<= 1) {
                mA = fmaxf(mA, __shfl_xor_sync(0xffffffffu, mA, o));
                mB = fmaxf(mB, __shfl_xor_sync(0xffffffffu, mB, o));
            }
            float sA = 0.f, sB = 0.f;
#pragma unroll
            for (int i = 0; i < 16; i++) {
                sA += __expf(vA[i] - mA);
                sB += __expf(vB[i] - mB);
            }
#pragma unroll
            for (int o = 1; o <= 2; o <<= 1) {
                sA += __shfl_xor_sync(0xffffffffu, sA, o);
                sB += __shfl_xor_sync(0xffffffffu, sB, o);
            }
            if (tig == 0) {
                sm_ls[(((wm * 2 + mt) * 2 + 0) * 8 + gid) * 2 + wn] =
                    make_float2(mA, sA);
                sm_ls[(((wm * 2 + mt) * 2 + 1) * 8 + gid) * 2 + wn] =
                    make_float2(mB, sB);
            }
            {
                int t = tgt[rA];
                int local = t - bn - wn * 64;
                if (local >= 0 && local < 64 && ((local >> 1) & 3) == tig)
                    g_tgtlog[rA] = vA[(local >> 3) * 2 + (local & 1)];
                t = tgt[rB];
                local = t - bn - wn * 64;
                if (local >= 0 && local < 64 && ((local >> 1) & 3) == tig)
                    g_tgtlog[rB] = vB[(local >> 3) * 2 + (local & 1)];
            }
        }
        __syncthreads();
        if (tid < 128) {
            int wm2 = tid >> 5, rest = tid & 31;
            int mt = rest >> 4, ab = (rest >> 3) & 1, gd = rest & 7;
            int row = bm + wm2 * 32 + mt * 16 + ab * 8 + gd;
            float2 h0 = sm_ls[(((wm2 * 2 + mt) * 2 + ab) * 8 + gd) * 2 + 0];
            float2 h1 = sm_ls[(((wm2 * 2 + mt) * 2 + ab) * 8 + gd) * 2 + 1];
            float mm = fmaxf(h0.x, h1.x);
            float ss = h0.y * __expf(h0.x - mm) + h1.y * __expf(h1.x - mm);
            g_ls[(size_t)row * (N >> 7) + blockIdx.x] = make_float2(mm, ss);
        }
        return;
    }

    // ---- standard epilogues ----
#pragma unroll
    for (int mt = 0; mt < 2; mt++) {
        int r0 = bm + wm * 32 + mt * 16 + gid;
#pragma unroll
        for (int nt = 0; nt < 8; nt++) {
            int col = bn + wn * 64 + nt * 8 + tig * 2;
            float v0 = acc[mt][nt][0], v1 = acc[mt][nt][1];
            float v2 = acc[mt][nt][2], v3 = acc[mt][nt][3];
            if (mode == 2) {
                bf16* hp0 = (bf16*)Cv + (size_t)r0 * N + col;
                bf16* hp1 = (bf16*)Cv + (size_t)(r0 + 8) * N + col;
                *reinterpret_cast<uint32_t*>(hp0) =
                    pack_bf16(v0 / (1.f + __expf(-v0)), v1 / (1.f + __expf(-v1)));
                *reinterpret_cast<uint32_t*>(hp1) =
                    pack_bf16(v2 / (1.f + __expf(-v2)), v3 / (1.f + __expf(-v3)));
            } else if (mode == 3) {
                bf16* hp0 = (bf16*)Cv + (size_t)r0 * N + col;
                bf16* hp1 = (bf16*)Cv + (size_t)(r0 + 8) * N + col;
                *reinterpret_cast<uint32_t*>(hp0) = pack_bf16(v0, v1);
                *reinterpret_cast<uint32_t*>(hp1) = pack_bf16(v2, v3);
            } else {
                float* p0 = (float*)Cv + (size_t)r0 * N + col;
                float* p1 = (float*)Cv + (size_t)(r0 + 8) * N + col;
                if (mode == 1) {
                    float2 o0 = *reinterpret_cast<float2*>(p0);
                    float2 o1 = *reinterpret_cast<float2*>(p1);
                    o0.x += alpha * v0; o0.y += alpha * v1;
                    o1.x += alpha * v2; o1.y += alpha * v3;
                    *reinterpret_cast<float2*>(p0) = o0;
                    *reinterpret_cast<float2*>(p1) = o1;
                } else {
                    *reinterpret_cast<float2*>(p0) = make_float2(alpha * v0, alpha * v1);
                    *reinterpret_cast<float2*>(p1) = make_float2(alpha * v2, alpha * v3);
                }
            }
        }
    }
}

// =====================================================================
// tensor-core flash attention (reverse-qt scheduling for load balance)
// =====================================================================
#define FA_QTILE  128
#define FA_KTILE  64
#define FA_QBYTES 16384u
#define FA_STAGE  16384u
#define FA_SMEM_BYTES (FA_QBYTES + 3*FA_STAGE)

__global__ __launch_bounds__(256, 1)
void flash_attn_tc() {
    extern __shared__ char smraw[];
    const uint32_t sQ = smem_u32(smraw);
    const int tid  = threadIdx.x;
    const int lane = tid & 31;
    const int wq   = tid >> 5;
    const int gid  = lane >> 2;
    const int tig  = lane & 3;
    const int lg   = lane >> 3;
    const int lgi  = lane & 7;
    const int qt = (gridDim.x - 1) - blockIdx.x;   // big tiles first
    const int h = blockIdx.y, b = blockIdx.z;

    const bf16* qkv = g_qkv;
    const size_t rowstride = 3 * D_;
    const size_t qbase = (size_t)(b * S_ + qt * FA_QTILE) * rowstride + h * HD_;

    {
#pragma unroll
        for (int i = 0; i < 4; i++) {
            int idx = tid + i * 256;
            int r = idx >> 3, ch = idx & 7;
            cp16(sQ + (uint32_t)r * 128u + (uint32_t)((ch ^ (r & 7)) << 4),
                 qkv + qbase + (size_t)r * rowstride + ch * 8);
        }
    }
    const int nK = 2 * (qt + 1);

#define FA_LOAD(kt, s) do {                                                  \
        size_t kbase = (size_t)(b * S_ + (kt) * FA_KTILE) * rowstride         \
                       + h * HD_ + D_;                                         \
        uint32_t base = sQ + FA_QBYTES + (uint32_t)(s) * FA_STAGE;            \
        _Pragma("unroll")                                                     \
        for (int i = 0; i < 2; i++) {                                         \
            int idx = tid + i * 256;                                          \
            int r = idx >> 3, ch = idx & 7;                                   \
            uint32_t sw = (uint32_t)((ch ^ (r & 7)) << 4);                    \
            cp16(base + (uint32_t)r * 128u + sw,                              \
                 qkv + kbase + (size_t)r * rowstride + ch * 8);               \
            cp16(base + 8192u + (uint32_t)r * 128u + sw,                      \
                 qkv + kbase + D_ + (size_t)r * rowstride + ch * 8);          \
        }                                                                     \
    } while (0)

    FA_LOAD(0, 0); CP_COMMIT();
    FA_LOAD(1, 1); CP_COMMIT();

    uint32_t aQ[4][4];
    float O[8][4];
#pragma unroll
    for (int dt = 0; dt < 8; dt++)
#pragma unroll
        for (int j = 0; j < 4; j++) O[dt][j] = 0.f;
    float m0 = -1e30f, m1 = -1e30f, l0 = 0.f, l1 = 0.f;
    const int qr0 = qt * FA_QTILE + wq * 16 + gid;
    bool qload = false;

    for (int kt = 0; kt < nK; kt++) {
        CP_WAIT1();
        __syncthreads();
        if (!qload) {
#pragma unroll
            for (int c = 0; c < 4; c++) {
                int row = wq * 16 + (lg & 1) * 8 + lgi;
                int chunk = c * 2 + (lg >> 1);
                ldsm4(aQ[c], sQ + (uint32_t)row * 128u +
                             (uint32_t)((chunk ^ (row & 7)) << 4));
            }
            qload = true;
        }
        if (kt + 2 < nK) FA_LOAD(kt + 2, (kt + 2) % 3);
        CP_COMMIT();

        const uint32_t sK = sQ + FA_QBYTES + (uint32_t)(kt % 3) * FA_STAGE;
        const uint32_t sV = sK + 8192u;

        float sc[8][4];
#pragma unroll
        for (int nt = 0; nt < 8; nt++)
#pragma unroll
            for (int j = 0; j < 4; j++) sc[nt][j] = 0.f;
#pragma unroll
        for (int c = 0; c < 4; c++) {
            uint32_t bK[8][2];
#pragma unroll
            for (int ntp = 0; ntp < 4; ntp++) {
                int row = ntp * 16 + lgi + (lg >> 1) * 8;
                int chunk = c * 2 + (lg & 1);
                uint32_t t4[4];
                ldsm4(t4, sK + (uint32_t)row * 128u +
                          (uint32_t)((chunk ^ (row & 7)) << 4));
                bK[2 * ntp][0] = t4[0]; bK[2 * ntp][1] = t4[1];
                bK[2 * ntp + 1][0] = t4[2]; bK[2 * ntp + 1][1] = t4[3];
            }
#pragma unroll
            for (int nt = 0; nt < 8; nt++)
                mma_bf16(sc[nt], aQ[c], bK[nt]);
        }

        const bool boundary = (kt >= 2 * qt);
#pragma unroll
        for (int nt = 0; nt < 8; nt++) {
            int key = kt * FA_KTILE + nt * 8 + tig * 2;
#pragma unroll
            for (int j = 0; j < 4; j++) {
                sc[nt][j] *= 0.125f;
                if (boundary) {
                    int kj = key + (j & 1);
                    int rq = qr0 + (j >> 1) * 8;
                    if (kj > rq) sc[nt][j] = -1e30f;
                }
            }
        }

        float rmax0 = -1e30f, rmax1 = -1e30f;
#pragma unroll
        for (int nt = 0; nt < 8; nt++) {
            rmax0 = fmaxf(rmax0, fmaxf(sc[nt][0], sc[nt][1]));
            rmax1 = fmaxf(rmax1, fmaxf(sc[nt][2], sc[nt][3]));
        }
#pragma unroll
        for (int o = 1; o <= 2; o <<= 1) {
            rmax0 = fmaxf(rmax0, __shfl_xor_sync(0xffffffffu, rmax0, o));
            rmax1 = fmaxf(rmax1, __shfl_xor_sync(0xffffffffu, rmax1, o));
        }
        float mn0 = fmaxf(m0, rmax0), mn1 = fmaxf(m1, rmax1);
        float c0 = __expf(m0 - mn0), c1 = __expf(m1 - mn1);
        float s0 = 0.f, s1 = 0.f;
        uint32_t pfr[8][2];
#pragma unroll
        for (int nt = 0; nt < 8; nt++) {
            float p0 = __expf(sc[nt][0] - mn0);
            float p1 = __expf(sc[nt][1] - mn0);
            float p2 = __expf(sc[nt][2] - mn1);
            float p3 = __expf(sc[nt][3] - mn1);
            s0 += p0 + p1; s1 += p2 + p3;
            pfr[nt][0] = pack_bf16(p0, p1);
            pfr[nt][1] = pack_bf16(p2, p3);
        }
#pragma unroll
        for (int o = 1; o <= 2; o <<= 1) {
            s0 += __shfl_xor_sync(0xffffffffu, s0, o);
            s1 += __shfl_xor_sync(0xffffffffu, s1, o);
        }
        l0 = l0 * c0 + s0;  l1 = l1 * c1 + s1;
        m0 = mn0; m1 = mn1;
#pragma unroll
        for (int dt = 0; dt < 8; dt++) {
            O[dt][0] *= c0; O[dt][1] *= c0;
            O[dt][2] *= c1; O[dt][3] *= c1;
        }

#pragma unroll
        for (int c = 0; c < 4; c++) {
            uint32_t aP[4] = { pfr[2 * c][0], pfr[2 * c][1],
                               pfr[2 * c + 1][0], pfr[2 * c + 1][1] };
            uint32_t bV[8][2];
#pragma unroll
            for (int dtp = 0; dtp < 4; dtp++) {
                int row = c * 16 + (lg & 1) * 8 + lgi;
                int chunk = dtp * 2 + (lg >> 1);
                uint32_t t4[4];
                ldsm4t(t4, sV + (uint32_t)row * 128u +
                           (uint32_t)((chunk ^ (row & 7)) << 4));
                bV[2 * dtp][0] = t4[0]; bV[2 * dtp][1] = t4[1];
                bV[2 * dtp + 1][0] = t4[2]; bV[2 * dtp + 1][1] = t4[3];
            }
#pragma unroll
            for (int dt = 0; dt < 8; dt++)
                mma_bf16(O[dt], aP, bV[dt]);
        }
    }

    float inv0 = 1.f / l0, inv1 = 1.f / l1;
    bf16* y0 = g_y + (size_t)(b * S_ + qr0) * D_ + h * HD_;
    bf16* y1 = y0 + (size_t)8 * D_;
#pragma unroll
    for (int dt = 0; dt < 8; dt++) {
        int col = dt * 8 + tig * 2;
        *reinterpret_cast<uint32_t*>(y0 + col) =
            pack_bf16(O[dt][0] * inv0, O[dt][1] * inv0);
        *reinterpret_cast<uint32_t*>(y1 + col) =
            pack_bf16(O[dt][2] * inv1, O[dt][3] * inv1);
    }
}

// =====================================================================
// conversion + non-GEMM kernels
// =====================================================================
__global__ void f2bf_kernel(const float* __restrict__ src,
                            bf16* __restrict__ dst, int n4) {
    int i = blockIdx.x * blockDim.x + threadIdx.x;
    if (i < n4) {
        float4 v = reinterpret_cast<const float4*>(src)[i];
        uint2 o = make_uint2(pack_bf16(v.x, v.y), pack_bf16(v.z, v.w));
        reinterpret_cast<uint2*>(dst)[i] = o;
    }
}

__global__ void embed_kernel(const int* __restrict__ ids,
                             const float* __restrict__ emb,
                             float* __restrict__ x) {
    int row = blockIdx.x;
    int id = ids[row];
    const float* src = emb + (size_t)id * D_;
    float* dst = x + (size_t)row * D_;
    for (int d = threadIdx.x; d < D_; d += blockDim.x) dst[d] = src[d];
}

__global__ void rmsnorm_kernel(const float* __restrict__ x,
                               const float* __restrict__ w,
                               bf16* __restrict__ y, float eps) {
    __shared__ float red[256];
    int row = blockIdx.x;
    const float* xr = x + (size_t)row * D_;
    float s = 0.f;
    for (int d = threadIdx.x; d < D_; d += 256) { float v = xr[d]; s += v * v; }
    red[threadIdx.x] = s; __syncthreads();
    for (int o = 128; o > 0; o >>= 1) {
        if (threadIdx.x < o) red[threadIdx.x] += red[threadIdx.x + o];
        __syncthreads();
    }
    float r = rsqrtf(red[0] / D_ + eps);
    bf16* yr = y + (size_t)row * D_;
    for (int d = threadIdx.x; d < D_; d += 256)
        yr[d] = __float2bfloat16(w[d] * xr[d] * r);
}

// q-RMS scalar: one warp per (row, head) -> g_rq[row*H + h]
__global__ void gdn_pre_q() {
    int gw = blockIdx.x * 8 + (threadIdx.x >> 5);
    int lid = threadIdx.x & 31;
    int row = gw >> 4;
    int h = gw & 15;
    size_t base = (size_t)row * (5 * D_) + h * 64;
    float q0 = g_proj[base + lid];
    float q1 = g_proj[base + 32 + lid];
    float s = q0 * q0 + q1 * q1;
#pragma unroll
    for (int o = 16; o > 0; o >>= 1) s += __shfl_xor_sync(0xffffffffu, s, o);
    if (lid == 0)
        g_rq[row * H_ + h] = rsqrtf(s / 64.f + QEPS_);
}

// ---- chunked gated scan: phase1 computes & stores u,a once (MUFU) ----
__global__ void scan_phase1() {
    int g = blockIdx.x * blockDim.x + threadIdx.x;
    int lane = g & 2047;
    int c = g >> 11;
    int b = lane >> 10, col = lane & 1023;
    float p = 1.f, acc = 0.f;
    int row0 = b * S_ + c * CHUNK_;
    for (int t = 0; t < CHUNK_; t++) {
        int row = row0 + t;
        size_t b5 = (size_t)row * (5 * D_);
        float kv = fast_tanh(g_proj[b5 + D_ + col]);
        float vv = g_proj[b5 + 2 * D_ + col];
        float a = fminf(fmaxf(fast_sig(g_proj[b5 + 3 * D_ + col] + 2.f),
                              0.6f), 0.9995f);
        float u = kv * vv;
        size_t idx = (size_t)row * D_ + col;
        g_u[idx] = u; g_a[idx] = a;
        p *= a;
        acc += u / fmaxf(p, 1e-6f);
    }
    g_scanP[g] = p; g_scanA[g] = acc;
}
__global__ void scan_phase2() {
    int lane = blockIdx.x * blockDim.x + threadIdx.x;
    float carry = 0.f;
    for (int c = 0; c < NCHUNK_; c++) {
        int i = c * 2048 + lane;
        g_scanC[i] = carry;
        carry = g_scanP[i] * (carry + g_scanA[i]);
    }
}
__global__ void scan_phase3_post() {
    int g = blockIdx.x * blockDim.x + threadIdx.x;
    int lane = g & 2047;
    int c = g >> 11;
    int b = lane >> 10, col = lane & 1023;
    float carry = g_scanC[g];
    float p = 1.f, acc = 0.f;
    int row0 = b * S_ + c * CHUNK_;
    const int hh = col >> 6;
    for (int t = 0; t < CHUNK_; t++) {
        int row = row0 + t;
        size_t idx = (size_t)row * D_ + col;
        p *= g_a[idx];
        acc += g_u[idx] / fmaxf(p, 1e-6f);
        float mem = p * (carry + acc);
        size_t b5 = (size_t)row * (5 * D_);
        float qh = g_proj[b5 + col] * g_rq[row * H_ + hh];
        float gate = fast_sig(g_proj[b5 + 4 * D_ + col]);
        float vv = g_proj[b5 + 2 * D_ + col];
        g_y[idx] = __float2bfloat16(gate * (qh * mem) + (1.f - gate) * vv);
    }
}

// ---- loss finalization ----
__global__ void loss_final() {
    __shared__ float mred[256], sred[256];
    int row = blockIdx.x;
    float2 v = g_ls[(size_t)row * 256 + threadIdx.x];
    mred[threadIdx.x] = v.x; sred[threadIdx.x] = v.y;
    __syncthreads();
    for (int o = 128; o > 0; o >>= 1) {
        if (threadIdx.x < o) {
            float m2 = mred[threadIdx.x + o], s2 = sred[threadIdx.x + o];
            float m1 = mred[threadIdx.x],     s1 = sred[threadIdx.x];
            float nm = fmaxf(m1, m2);
            mred[threadIdx.x] = nm;
            sred[threadIdx.x] = s1 * __expf(m1 - nm) + s2 * __expf(m2 - nm);
        }
        __syncthreads();
    }
    if (threadIdx.x == 0)
        g_rowloss[row] = -(g_tgtlog[row] - mred[0] - logf(sred[0]));
}

__global__ void loss_reduce_kernel(float* __restrict__ out) {
    __shared__ float red[256];
    float s = 0.f;
    for (int i = threadIdx.x; i < BS_; i += 256) s += g_rowloss[i];
    red[threadIdx.x] = s; __syncthreads();
    for (int o = 128; o > 0; o >>= 1) {
        if (threadIdx.x < o) red[threadIdx.x] += red[threadIdx.x + o];
        __syncthreads();
    }
    if (threadIdx.x == 0) out[0] = red[0] / (float)BS_;
}

// =====================================================================
// host orchestration
// =====================================================================
static void launch_gemm(const bf16* A, const bf16* W, void* C,
                        int M, int N, int K, float alpha, int mode,
                        const float* bias = nullptr, const int* tgt = nullptr) {
    dim3 grid(N / 128, M / 128);
    gemm_tc<<<grid, 256, GT_SMEM_BYTES>>>(A, W, C, M, N, K, alpha, mode, bias, tgt);
}
static void convert(const float* src, bf16* dst, size_t n) {
    int n4 = (int)(n / 4);
    f2bf_kernel<<<(n4 + 255) / 256, 256>>>(src, dst, n4);
}

extern "C" void kernel_launch(void* const* d_in, const int* in_sizes, int n_in,
                              void* d_out, int out_size) {
    const int*   input_ids   = (const int*)  d_in[0];
    const int*   target_ids  = (const int*)  d_in[1];
    const float* tok_emb     = (const float*)d_in[2];
    const float* lm_bias     = (const float*)d_in[3];
    const float* gdn_in_w    = (const float*)d_in[4];
    const float* gdn_out_w   = (const float*)d_in[5];
    const float* gdn_norm1   = (const float*)d_in[6];
    const float* gdn_norm2   = (const float*)d_in[7];
    const float* gdn_fc_w    = (const float*)d_in[8];
    const float* gdn_proj_w  = (const float*)d_in[9];
    const float* attn_qkv_w  = (const float*)d_in[10];
    const float* attn_proj_w = (const float*)d_in[11];
    const float* attn_norm1  = (const float*)d_in[12];
    const float* attn_norm2  = (const float*)d_in[13];
    const float* attn_fc_w   = (const float*)d_in[14];
    const float* attn_mlp_w  = (const float*)d_in[15];
    const float* final_norm  = (const float*)d_in[16];
    float* out = (float*)d_out;

    cudaFuncSetAttribute(gemm_tc, cudaFuncAttributeMaxDynamicSharedMemorySize,
                         GT_SMEM_BYTES);
    cudaFuncSetAttribute(flash_attn_tc, cudaFuncAttributeMaxDynamicSharedMemorySize,
                         FA_SMEM_BYTES);

    float *x, *proj;
    bf16 *xn, *y, *hid, *qkvb;
    bf16 *bw_in, *bw_out, *bw_fc, *bw_pj, *bw_qkv, *bw_apj, *bw_afc, *bw_ampj, *bw_emb;
    cudaGetSymbolAddress((void**)&x,      g_x);
    cudaGetSymbolAddress((void**)&xn,     g_xn);
    cudaGetSymbolAddress((void**)&proj,   g_proj);
    cudaGetSymbolAddress((void**)&y,      g_y);
    cudaGetSymbolAddress((void**)&hid,    g_hid);
    cudaGetSymbolAddress((void**)&qkvb,   g_qkv);
    cudaGetSymbolAddress((void**)&bw_in,   w_gdn_in);
    cudaGetSymbolAddress((void**)&bw_out,  w_gdn_out);
    cudaGetSymbolAddress((void**)&bw_fc,   w_gdn_fc);
    cudaGetSymbolAddress((void**)&bw_pj,   w_gdn_pj);
    cudaGetSymbolAddress((void**)&bw_qkv,  w_qkv);
    cudaGetSymbolAddress((void**)&bw_apj,  w_apj);
    cudaGetSymbolAddress((void**)&bw_afc,  w_afc);
    cudaGetSymbolAddress((void**)&bw_ampj, w_ampj);
    cudaGetSymbolAddress((void**)&bw_emb,  w_emb);

    convert(gdn_in_w,   bw_in,   (size_t)LG_ * 5 * D_ * D_);
    convert(gdn_out_w,  bw_out,  (size_t)LG_ * D_ * D_);
    convert(gdn_fc_w,   bw_fc,   (size_t)LG_ * HM_ * D_);
    convert(gdn_proj_w, bw_pj,   (size_t)LG_ * D_ * HM_);
    convert(attn_qkv_w, bw_qkv,  (size_t)3 * D_ * D_);
    convert(attn_proj_w, bw_apj, (size_t)D_ * D_);
    convert(attn_fc_w,  bw_afc,  (size_t)HM_ * D_);
    convert(attn_mlp_w, bw_ampj, (size_t)D_ * HM_);
    convert(tok_emb,    bw_emb,  (size_t)V_ * D_);

    embed_kernel<<<BS_, 256>>>(input_ids, tok_emb, x);

    for (int i = 0; i < LG_; i++) {
        float rsc = rsqrtf(2.0f * (i + 1));
        rmsnorm_kernel<<<BS_, 256>>>(x, gdn_norm1 + (size_t)i * D_, xn, 1e-6f);
        launch_gemm(xn, bw_in + (size_t)i * 5 * D_ * D_, proj, BS_, 5 * D_, D_, 1.f, 0);
        gdn_pre_q<<<BS_ * H_ / 8, 256>>>();
        scan_phase1<<<B_ * D_ * NCHUNK_ / 256, 256>>>();
        scan_phase2<<<B_ * D_ / 256, 256>>>();
        scan_phase3_post<<<B_ * D_ * NCHUNK_ / 256, 256>>>();
        launch_gemm(y, bw_out + (size_t)i * D_ * D_, x, BS_, D_, D_, rsc, 1);
        rmsnorm_kernel<<<BS_, 256>>>(x, gdn_norm2 + (size_t)i * D_, xn, 1e-6f);
        launch_gemm(xn, bw_fc + (size_t)i * HM_ * D_, hid, BS_, HM_, D_, 1.f, 2);
        launch_gemm(hid, bw_pj + (size_t)i * D_ * HM_, x, BS_, D_, HM_, rsc, 1);
    }

    float rsc = rsqrtf(2.0f * (LG_ + 1));
    rmsnorm_kernel<<<BS_, 256>>>(x, attn_norm1, xn, 1e-6f);
    launch_gemm(xn, bw_qkv, qkvb, BS_, 3 * D_, D_, 1.f, 3);
    {
        dim3 fgrid(S_ / FA_QTILE, H_, B_);
        flash_attn_tc<<<fgrid, 256, FA_SMEM_BYTES>>>();
    }
    launch_gemm(y, bw_apj, x, BS_, D_, D_, rsc, 1);
    rmsnorm_kernel<<<BS_, 256>>>(x, attn_norm2, xn, 1e-6f);
    launch_gemm(xn, bw_afc, hid, BS_, HM_, D_, 1.f, 2);
    launch_gemm(hid, bw_ampj, x, BS_, D_, HM_, rsc, 1);

    rmsnorm_kernel<<<BS_, 256>>>(x, final_norm, xn, 1e-6f);
    launch_gemm(xn, bw_emb, nullptr, BS_, V_, D_, 1.f, 4, lm_bias, target_ids);
    loss_final<<<BS_, 256>>>();
    loss_reduce_kernel<<<1, 256>>>(out);
}

// round 14
// speedup vs baseline: 1.1236x; 1.1236x over previous
#include <cuda_runtime.h>
#include <cuda_bf16.h>
#include <math.h>
#include <stdint.h>

// ---------------- problem constants ----------------
#define B_      2
#define S_      2048
#define BS_     (B_*S_)          // 4096 token rows
#define D_      1024
#define H_      16
#define HD_     64
#define HM_     4096
#define V_      32768
#define LG_     8
#define CHUNK_  64
#define NCHUNK_ (S_/CHUNK_)      // 32
#define QEPS_   1.1920929e-07f

typedef __nv_bfloat16 bf16;

// ---------------- static device scratch ----------------
__device__ float g_x   [BS_*D_];
__device__ bf16  g_xn  [BS_*D_];
__device__ float g_proj[BS_*5*D_];
__device__ float g_rq  [BS_*H_];        // per-(row,head) q-rms reciprocal
__device__ bf16  g_y   [BS_*D_];
__device__ bf16  g_hid [BS_*HM_];
__device__ bf16  g_qkv [BS_*3*D_];
__device__ float g_scanP[B_*D_*NCHUNK_];
__device__ float g_scanA[B_*D_*NCHUNK_];
__device__ float g_scanC[B_*D_*NCHUNK_];
__device__ float2 g_ls[BS_*(V_/128)];
__device__ float g_tgtlog[BS_];
__device__ float g_rowloss[BS_];

// bf16 weight mirrors (converted once per launch)
__device__ bf16 w_gdn_in [LG_*5*D_*D_];
__device__ bf16 w_gdn_out[LG_*D_*D_];
__device__ bf16 w_gdn_fc [LG_*HM_*D_];
__device__ bf16 w_gdn_pj [LG_*D_*HM_];
__device__ bf16 w_qkv    [3*D_*D_];
__device__ bf16 w_apj    [D_*D_];
__device__ bf16 w_afc    [HM_*D_];
__device__ bf16 w_ampj   [D_*HM_];
__device__ bf16 w_emb    [(size_t)V_*D_];

// =====================================================================
// helpers
// =====================================================================
__device__ __forceinline__ uint32_t smem_u32(const void* p) {
    uint32_t a;
    asm("{ .reg .u64 t; cvta.to.shared.u64 t, %1; cvt.u32.u64 %0, t; }"
        : "=r"(a) : "l"(p));
    return a;
}
__device__ __forceinline__ uint32_t pack_bf16(float lo, float hi) {
    __nv_bfloat162 h = __floats2bfloat162_rn(lo, hi);
    return *reinterpret_cast<uint32_t*>(&h);
}
__device__ __forceinline__ void cp16(uint32_t dst, const void* src) {
    asm volatile("cp.async.cg.shared.global [%0], [%1], 16;"
                 :: "r"(dst), "l"(src) : "memory");
}
#define CP_COMMIT() asm volatile("cp.async.commit_group;" ::: "memory")
#define CP_WAIT1()  asm volatile("cp.async.wait_group 1;" ::: "memory")

__device__ __forceinline__ void ldsm4(uint32_t r[4], uint32_t addr) {
    asm volatile("ldmatrix.sync.aligned.m8n8.x4.shared.b16 {%0,%1,%2,%3}, [%4];"
                 : "=r"(r[0]), "=r"(r[1]), "=r"(r[2]), "=r"(r[3]) : "r"(addr));
}
__device__ __forceinline__ void ldsm4t(uint32_t r[4], uint32_t addr) {
    asm volatile("ldmatrix.sync.aligned.m8n8.x4.trans.shared.b16 {%0,%1,%2,%3}, [%4];"
                 : "=r"(r[0]), "=r"(r[1]), "=r"(r[2]), "=r"(r[3]) : "r"(addr));
}
__device__ __forceinline__ void mma_bf16(float c[4], const uint32_t a[4],
                                         const uint32_t b[2]) {
    asm volatile(
        "mma.sync.aligned.m16n8k16.row.col.f32.bf16.bf16.f32 "
        "{%0,%1,%2,%3}, {%4,%5,%6,%7}, {%8,%9}, {%0,%1,%2,%3};"
        : "+f"(c[0]), "+f"(c[1]), "+f"(c[2]), "+f"(c[3])
        : "r"(a[0]), "r"(a[1]), "r"(a[2]), "r"(a[3]), "r"(b[0]), "r"(b[1]));
}

// =====================================================================
// bf16 GEMM: C[M,N] = op(alpha * A[M,K] @ W[N,K]^T)
// mode: 0 fp32 overwrite, 1 fp32 accumulate, 2 bf16 silu, 3 bf16 overwrite,
//       4 logsumexp-partial epilogue (LM head + loss fusion)
// =====================================================================
#define TILE_B  16384u
#define STAGE_B 32768u
#define GT_SMEM_BYTES (3*STAGE_B) // 98304

__global__ __launch_bounds__(256, 2)
void gemm_tc(const bf16* __restrict__ A, const bf16* __restrict__ W,
             void* __restrict__ Cv, int M, int N, int K, float alpha, int mode,
             const float* __restrict__ bias, const int* __restrict__ tgt) {
    extern __shared__ char smraw[];
    const uint32_t sb = smem_u32(smraw);
    const int tid  = threadIdx.x;
    const int lane = tid & 31;
    const int wid  = tid >> 5;
    const int wm   = wid & 3;
    const int wn   = wid >> 2;
    const int bm   = blockIdx.y * 128, bn = blockIdx.x * 128;
    const int gid  = lane >> 2;
    const int tig  = lane & 3;

    float acc[2][8][4];
#pragma unroll
    for (int mt = 0; mt < 2; mt++)
#pragma unroll
        for (int nt = 0; nt < 8; nt++)
#pragma unroll
            for (int j = 0; j < 4; j++) acc[mt][nt][j] = 0.f;

    const int nIter = K >> 6;
    const int lrow  = tid >> 3;
    const int lc    = tid & 7;

#define LOAD_STAGE(it, s) do {                                               \
        int k0 = (it) * 64;                                                   \
        uint32_t base = sb + (uint32_t)(s) * STAGE_B;                         \
        _Pragma("unroll")                                                     \
        for (int i = 0; i < 4; i++) {                                         \
            int r = lrow + i * 32;                                            \
            uint32_t sw = (uint32_t)((lc ^ (r & 7)) << 4);                    \
            cp16(base + (uint32_t)r * 128u + sw,                              \
                 A + (size_t)(bm + r) * K + k0 + lc * 8);                     \
            cp16(base + TILE_B + (uint32_t)r * 128u + sw,                     \
                 W + (size_t)(bn + r) * K + k0 + lc * 8);                     \
        }                                                                     \
    } while (0)

    LOAD_STAGE(0, 0); CP_COMMIT();
    LOAD_STAGE(1, 1); CP_COMMIT();

    const int lg  = lane >> 3;
    const int lgi = lane & 7;

    for (int it = 0; it < nIter; it++) {
        CP_WAIT1();
        __syncthreads();
        if (it + 2 < nIter) LOAD_STAGE(it + 2, (it + 2) % 3);
        CP_COMMIT();

        const uint32_t sA = sb + (uint32_t)(it % 3) * STAGE_B;
        const uint32_t sW = sA + TILE_B;

#pragma unroll
        for (int kk = 0; kk < 4; kk++) {
            uint32_t afr[2][4], bfr[8][2];
#pragma unroll
            for (int mt = 0; mt < 2; mt++) {
                int row = wm * 32 + mt * 16 + lgi + (lg & 1) * 8;
                int chunk = kk * 2 + (lg >> 1);
                ldsm4(afr[mt], sA + (uint32_t)row * 128u +
                               (uint32_t)((chunk ^ (row & 7)) << 4));
            }
#pragma unroll
            for (int ntp = 0; ntp < 4; ntp++) {
                int row = wn * 64 + ntp * 16 + lgi + (lg >> 1) * 8;
                int chunk = kk * 2 + (lg & 1);
                uint32_t t4[4];
                ldsm4(t4, sW + (uint32_t)row * 128u +
                          (uint32_t)((chunk ^ (row & 7)) << 4));
                bfr[2 * ntp][0] = t4[0]; bfr[2 * ntp][1] = t4[1];
                bfr[2 * ntp + 1][0] = t4[2]; bfr[2 * ntp + 1][1] = t4[3];
            }
#pragma unroll
            for (int mt = 0; mt < 2; mt++)
#pragma unroll
                for (int nt = 0; nt < 8; nt++)
                    mma_bf16(acc[mt][nt], afr[mt], bfr[nt]);
        }
    }

    if (mode == 4) {
        // ---- fused logsumexp-partial epilogue (LM head) ----
        __syncthreads();
        float2* sm_ls = reinterpret_cast<float2*>(smraw);
#pragma unroll
        for (int mt = 0; mt < 2; mt++) {
            int rA = bm + wm * 32 + mt * 16 + gid;
            int rB = rA + 8;
            float vA[16], vB[16];
            float mA = -1e30f, mB = -1e30f;
#pragma unroll
            for (int nt = 0; nt < 8; nt++) {
                int col = bn + wn * 64 + nt * 8 + tig * 2;
                float2 bv = *reinterpret_cast<const float2*>(bias + col);
                vA[2 * nt]     = acc[mt][nt][0] + bv.x;
                vA[2 * nt + 1] = acc[mt][nt][1] + bv.y;
                vB[2 * nt]     = acc[mt][nt][2] + bv.x;
                vB[2 * nt + 1] = acc[mt][nt][3] + bv.y;
                mA = fmaxf(mA, fmaxf(vA[2 * nt], vA[2 * nt + 1]));
                mB = fmaxf(mB, fmaxf(vB[2 * nt], vB[2 * nt + 1]));
            }
#pragma unroll
            for (int o = 1; o <= 2; o <<= 1) {
                mA = fmaxf(mA, __shfl_xor_sync(0xffffffffu, mA, o));
                mB = fmaxf(mB, __shfl_xor_sync(0xffffffffu, mB, o));
            }
            float sA = 0.f, sB = 0.f;
#pragma unroll
            for (int i = 0; i < 16; i++) {
                sA += __expf(vA[i] - mA);
                sB += __expf(vB[i] - mB);
            }
#pragma unroll
            for (int o = 1; o <= 2; o <<= 1) {
                sA += __shfl_xor_sync(0xffffffffu, sA, o);
                sB += __shfl_xor_sync(0xffffffffu, sB, o);
            }
            if (tig == 0) {
                sm_ls[(((wm * 2 + mt) * 2 + 0) * 8 + gid) * 2 + wn] =
                    make_float2(mA, sA);
                sm_ls[(((wm * 2 + mt) * 2 + 1) * 8 + gid) * 2 + wn] =
                    make_float2(mB, sB);
            }
            // capture target logit (exactly one thread grid-wide per row)
            {
                int t = tgt[rA];
                int local = t - bn - wn * 64;
                if (local >= 0 && local < 64 && ((local >> 1) & 3) == tig)
                    g_tgtlog[rA] = vA[(local >> 3) * 2 + (local & 1)];
                t = tgt[rB];
                local = t - bn - wn * 64;
                if (local >= 0 && local < 64 && ((local >> 1) & 3) == tig)
                    g_tgtlog[rB] = vB[(local >> 3) * 2 + (local & 1)];
            }
        }
        __syncthreads();
        if (tid < 128) {
            int wm2 = tid >> 5, rest = tid & 31;
            int mt = rest >> 4, ab = (rest >> 3) & 1, gd = rest & 7;
            int row = bm + wm2 * 32 + mt * 16 + ab * 8 + gd;
            float2 h0 = sm_ls[(((wm2 * 2 + mt) * 2 + ab) * 8 + gd) * 2 + 0];
            float2 h1 = sm_ls[(((wm2 * 2 + mt) * 2 + ab) * 8 + gd) * 2 + 1];
            float mm = fmaxf(h0.x, h1.x);
            float ss = h0.y * __expf(h0.x - mm) + h1.y * __expf(h1.x - mm);
            g_ls[(size_t)row * (N >> 7) + blockIdx.x] = make_float2(mm, ss);
        }
        return;
    }

    // ---- standard epilogues ----
#pragma unroll
    for (int mt = 0; mt < 2; mt++) {
        int r0 = bm + wm * 32 + mt * 16 + gid;
#pragma unroll
        for (int nt = 0; nt < 8; nt++) {
            int col = bn + wn * 64 + nt * 8 + tig * 2;
            float v0 = acc[mt][nt][0], v1 = acc[mt][nt][1];
            float v2 = acc[mt][nt][2], v3 = acc[mt][nt][3];
            if (mode == 2) {
                bf16* hp0 = (bf16*)Cv + (size_t)r0 * N + col;
                bf16* hp1 = (bf16*)Cv + (size_t)(r0 + 8) * N + col;
                *reinterpret_cast<uint32_t*>(hp0) =
                    pack_bf16(v0 / (1.f + __expf(-v0)), v1 / (1.f + __expf(-v1)));
                *reinterpret_cast<uint32_t*>(hp1) =
                    pack_bf16(v2 / (1.f + __expf(-v2)), v3 / (1.f + __expf(-v3)));
            } else if (mode == 3) {
                bf16* hp0 = (bf16*)Cv + (size_t)r0 * N + col;
                bf16* hp1 = (bf16*)Cv + (size_t)(r0 + 8) * N + col;
                *reinterpret_cast<uint32_t*>(hp0) = pack_bf16(v0, v1);
                *reinterpret_cast<uint32_t*>(hp1) = pack_bf16(v2, v3);
            } else {
                float* p0 = (float*)Cv + (size_t)r0 * N + col;
                float* p1 = (float*)Cv + (size_t)(r0 + 8) * N + col;
                if (mode == 1) {
                    float2 o0 = *reinterpret_cast<float2*>(p0);
                    float2 o1 = *reinterpret_cast<float2*>(p1);
                    o0.x += alpha * v0; o0.y += alpha * v1;
                    o1.x += alpha * v2; o1.y += alpha * v3;
                    *reinterpret_cast<float2*>(p0) = o0;
                    *reinterpret_cast<float2*>(p1) = o1;
                } else {
                    *reinterpret_cast<float2*>(p0) = make_float2(alpha * v0, alpha * v1);
                    *reinterpret_cast<float2*>(p1) = make_float2(alpha * v2, alpha * v3);
                }
            }
        }
    }
}

// =====================================================================
// tensor-core flash attention (reverse-qt scheduling for load balance)
// =====================================================================
#define FA_QTILE  128
#define FA_KTILE  64
#define FA_QBYTES 16384u
#define FA_STAGE  16384u
#define FA_SMEM_BYTES (FA_QBYTES + 3*FA_STAGE)

__global__ __launch_bounds__(256, 1)
void flash_attn_tc() {
    extern __shared__ char smraw[];
    const uint32_t sQ = smem_u32(smraw);
    const int tid  = threadIdx.x;
    const int lane = tid & 31;
    const int wq   = tid >> 5;
    const int gid  = lane >> 2;
    const int tig  = lane & 3;
    const int lg   = lane >> 3;
    const int lgi  = lane & 7;
    const int qt = (gridDim.x - 1) - blockIdx.x;   // big tiles first
    const int h = blockIdx.y, b = blockIdx.z;

    const bf16* qkv = g_qkv;
    const size_t rowstride = 3 * D_;
    const size_t qbase = (size_t)(b * S_ + qt * FA_QTILE) * rowstride + h * HD_;

    {
#pragma unroll
        for (int i = 0; i < 4; i++) {
            int idx = tid + i * 256;
            int r = idx >> 3, ch = idx & 7;
            cp16(sQ + (uint32_t)r * 128u + (uint32_t)((ch ^ (r & 7)) << 4),
                 qkv + qbase + (size_t)r * rowstride + ch * 8);
        }
    }
    const int nK = 2 * (qt + 1);

#define FA_LOAD(kt, s) do {                                                  \
        size_t kbase = (size_t)(b * S_ + (kt) * FA_KTILE) * rowstride         \
                       + h * HD_ + D_;                                         \
        uint32_t base = sQ + FA_QBYTES + (uint32_t)(s) * FA_STAGE;            \
        _Pragma("unroll")                                                     \
        for (int i = 0; i < 2; i++) {                                         \
            int idx = tid + i * 256;                                          \
            int r = idx >> 3, ch = idx & 7;                                   \
            uint32_t sw = (uint32_t)((ch ^ (r & 7)) << 4);                    \
            cp16(base + (uint32_t)r * 128u + sw,                              \
                 qkv + kbase + (size_t)r * rowstride + ch * 8);               \
            cp16(base + 8192u + (uint32_t)r * 128u + sw,                      \
                 qkv + kbase + D_ + (size_t)r * rowstride + ch * 8);          \
        }                                                                     \
    } while (0)

    FA_LOAD(0, 0); CP_COMMIT();
    FA_LOAD(1, 1); CP_COMMIT();

    uint32_t aQ[4][4];
    float O[8][4];
#pragma unroll
    for (int dt = 0; dt < 8; dt++)
#pragma unroll
        for (int j = 0; j < 4; j++) O[dt][j] = 0.f;
    float m0 = -1e30f, m1 = -1e30f, l0 = 0.f, l1 = 0.f;
    const int qr0 = qt * FA_QTILE + wq * 16 + gid;
    bool qload = false;

    for (int kt = 0; kt < nK; kt++) {
        CP_WAIT1();
        __syncthreads();
        if (!qload) {
#pragma unroll
            for (int c = 0; c < 4; c++) {
                int row = wq * 16 + (lg & 1) * 8 + lgi;
                int chunk = c * 2 + (lg >> 1);
                ldsm4(aQ[c], sQ + (uint32_t)row * 128u +
                             (uint32_t)((chunk ^ (row & 7)) << 4));
            }
            qload = true;
        }
        if (kt + 2 < nK) FA_LOAD(kt + 2, (kt + 2) % 3);
        CP_COMMIT();

        const uint32_t sK = sQ + FA_QBYTES + (uint32_t)(kt % 3) * FA_STAGE;
        const uint32_t sV = sK + 8192u;

        float sc[8][4];
#pragma unroll
        for (int nt = 0; nt < 8; nt++)
#pragma unroll
            for (int j = 0; j < 4; j++) sc[nt][j] = 0.f;
#pragma unroll
        for (int c = 0; c < 4; c++) {
            uint32_t bK[8][2];
#pragma unroll
            for (int ntp = 0; ntp < 4; ntp++) {
                int row = ntp * 16 + lgi + (lg >> 1) * 8;
                int chunk = c * 2 + (lg & 1);
                uint32_t t4[4];
                ldsm4(t4, sK + (uint32_t)row * 128u +
                          (uint32_t)((chunk ^ (row & 7)) << 4));
                bK[2 * ntp][0] = t4[0]; bK[2 * ntp][1] = t4[1];
                bK[2 * ntp + 1][0] = t4[2]; bK[2 * ntp + 1][1] = t4[3];
            }
#pragma unroll
            for (int nt = 0; nt < 8; nt++)
                mma_bf16(sc[nt], aQ[c], bK[nt]);
        }

        const bool boundary = (kt >= 2 * qt);
#pragma unroll
        for (int nt = 0; nt < 8; nt++) {
            int key = kt * FA_KTILE + nt * 8 + tig * 2;
#pragma unroll
            for (int j = 0; j < 4; j++) {
                sc[nt][j] *= 0.125f;
                if (boundary) {
                    int kj = key + (j & 1);
                    int rq = qr0 + (j >> 1) * 8;
                    if (kj > rq) sc[nt][j] = -1e30f;
                }
            }
        }

        float rmax0 = -1e30f, rmax1 = -1e30f;
#pragma unroll
        for (int nt = 0; nt < 8; nt++) {
            rmax0 = fmaxf(rmax0, fmaxf(sc[nt][0], sc[nt][1]));
            rmax1 = fmaxf(rmax1, fmaxf(sc[nt][2], sc[nt][3]));
        }
#pragma unroll
        for (int o = 1; o <= 2; o <<= 1) {
            rmax0 = fmaxf(rmax0, __shfl_xor_sync(0xffffffffu, rmax0, o));
            rmax1 = fmaxf(rmax1, __shfl_xor_sync(0xffffffffu, rmax1, o));
        }
        float mn0 = fmaxf(m0, rmax0), mn1 = fmaxf(m1, rmax1);
        float c0 = __expf(m0 - mn0), c1 = __expf(m1 - mn1);
        float s0 = 0.f, s1 = 0.f;
        uint32_t pfr[8][2];
#pragma unroll
        for (int nt = 0; nt < 8; nt++) {
            float p0 = __expf(sc[nt][0] - mn0);
            float p1 = __expf(sc[nt][1] - mn0);
            float p2 = __expf(sc[nt][2] - mn1);
            float p3 = __expf(sc[nt][3] - mn1);
            s0 += p0 + p1; s1 += p2 + p3;
            pfr[nt][0] = pack_bf16(p0, p1);
            pfr[nt][1] = pack_bf16(p2, p3);
        }
#pragma unroll
        for (int o = 1; o <= 2; o <<= 1) {
            s0 += __shfl_xor_sync(0xffffffffu, s0, o);
            s1 += __shfl_xor_sync(0xffffffffu, s1, o);
        }
        l0 = l0 * c0 + s0;  l1 = l1 * c1 + s1;
        m0 = mn0; m1 = mn1;
#pragma unroll
        for (int dt = 0; dt < 8; dt++) {
            O[dt][0] *= c0; O[dt][1] *= c0;
            O[dt][2] *= c1; O[dt][3] *= c1;
        }

#pragma unroll
        for (int c = 0; c < 4; c++) {
            uint32_t aP[4] = { pfr[2 * c][0], pfr[2 * c][1],
                               pfr[2 * c + 1][0], pfr[2 * c + 1][1] };
            uint32_t bV[8][2];
#pragma unroll
            for (int dtp = 0; dtp < 4; dtp++) {
                int row = c * 16 + (lg & 1) * 8 + lgi;
                int chunk = dtp * 2 + (lg >> 1);
                uint32_t t4[4];
                ldsm4t(t4, sV + (uint32_t)row * 128u +
                           (uint32_t)((chunk ^ (row & 7)) << 4));
                bV[2 * dtp][0] = t4[0]; bV[2 * dtp][1] = t4[1];
                bV[2 * dtp + 1][0] = t4[2]; bV[2 * dtp + 1][1] = t4[3];
            }
#pragma unroll
            for (int dt = 0; dt < 8; dt++)
                mma_bf16(O[dt], aP, bV[dt]);
        }
    }

    float inv0 = 1.f / l0, inv1 = 1.f / l1;
    bf16* y0 = g_y + (size_t)(b * S_ + qr0) * D_ + h * HD_;
    bf16* y1 = y0 + (size_t)8 * D_;
#pragma unroll
    for (int dt = 0; dt < 8; dt++) {
        int col = dt * 8 + tig * 2;
        *reinterpret_cast<uint32_t*>(y0 + col) =
            pack_bf16(O[dt][0] * inv0, O[dt][1] * inv0);
        *reinterpret_cast<uint32_t*>(y1 + col) =
            pack_bf16(O[dt][2] * inv1, O[dt][3] * inv1);
    }
}

// =====================================================================
// conversion + non-GEMM kernels
// =====================================================================
__global__ void f2bf_kernel(const float* __restrict__ src,
                            bf16* __restrict__ dst, int n4) {
    int i = blockIdx.x * blockDim.x + threadIdx.x;
    if (i < n4) {
        float4 v = reinterpret_cast<const float4*>(src)[i];
        uint2 o = make_uint2(pack_bf16(v.x, v.y), pack_bf16(v.z, v.w));
        reinterpret_cast<uint2*>(dst)[i] = o;
    }
}

__global__ void embed_kernel(const int* __restrict__ ids,
                             const float* __restrict__ emb,
                             float* __restrict__ x) {
    int row = blockIdx.x;
    int id = ids[row];
    const float* src = emb + (size_t)id * D_;
    float* dst = x + (size_t)row * D_;
    for (int d = threadIdx.x; d < D_; d += blockDim.x) dst[d] = src[d];
}

// vectorized rmsnorm: one float4 per thread (256 threads x 4 = D)
__global__ void rmsnorm_kernel(const float* __restrict__ x,
                               const float* __restrict__ w,
                               bf16* __restrict__ y, float eps) {
    __shared__ float red[8];
    int row = blockIdx.x;
    int tid = threadIdx.x;
    float4 v = reinterpret_cast<const float4*>(x + (size_t)row * D_)[tid];
    float s = v.x * v.x + v.y * v.y + v.z * v.z + v.w * v.w;
#pragma unroll
    for (int o = 16; o > 0; o >>= 1) s += __shfl_xor_sync(0xffffffffu, s, o);
    if ((tid & 31) == 0) red[tid >> 5] = s;
    __syncthreads();
    float tot = red[0];
#pragma unroll
    for (int i = 1; i < 8; i++) tot += red[i];
    float r = rsqrtf(tot / D_ + eps);
    float4 wv = reinterpret_cast<const float4*>(w)[tid];
    uint2 o = make_uint2(pack_bf16(wv.x * v.x * r, wv.y * v.y * r),
                         pack_bf16(wv.z * v.z * r, wv.w * v.w * r));
    reinterpret_cast<uint2*>(y + (size_t)row * D_)[tid] = o;
}

// q-RMS scalar: one warp per (row, head) -> g_rq[row*H + h]
__global__ void gdn_pre_q() {
    int gw = blockIdx.x * 8 + (threadIdx.x >> 5);
    int lid = threadIdx.x & 31;
    int row = gw >> 4;
    int h = gw & 15;
    size_t base = (size_t)row * (5 * D_) + h * 64;
    float q0 = g_proj[base + lid];
    float q1 = g_proj[base + 32 + lid];
    float s = q0 * q0 + q1 * q1;
#pragma unroll
    for (int o = 16; o > 0; o >>= 1) s += __shfl_xor_sync(0xffffffffu, s, o);
    if (lid == 0)
        g_rq[row * H_ + h] = rsqrtf(s / 64.f + QEPS_);
}

// ---- chunked gated scan (u,a recomputed from proj) ----
__device__ __forceinline__ void gdn_ua(size_t b5, int col, float& a, float& u) {
    float kv = tanhf(g_proj[b5 + D_ + col]);
    float vv = g_proj[b5 + 2 * D_ + col];
    float av = 1.f / (1.f + expf(-(g_proj[b5 + 3 * D_ + col] + 2.f)));
    a = fminf(fmaxf(av, 0.6f), 0.9995f);
    u = kv * vv;
}

__global__ void scan_phase1() {
    int g = blockIdx.x * blockDim.x + threadIdx.x;
    int lane = g & 2047;
    int c = g >> 11;
    int b = lane >> 10, col = lane & 1023;
    float p = 1.f, acc = 0.f;
    int row0 = b * S_ + c * CHUNK_;
    for (int t = 0; t < CHUNK_; t++) {
        size_t b5 = (size_t)(row0 + t) * (5 * D_);
        float a, u;
        gdn_ua(b5, col, a, u);
        p *= a;
        acc += u / fmaxf(p, 1e-6f);
    }
    g_scanP[g] = p; g_scanA[g] = acc;
}
__global__ void scan_phase2() {
    int lane = blockIdx.x * blockDim.x + threadIdx.x;
    float carry = 0.f;
    for (int c = 0; c < NCHUNK_; c++) {
        int i = c * 2048 + lane;
        g_scanC[i] = carry;
        carry = g_scanP[i] * (carry + g_scanA[i]);
    }
}
__global__ void scan_phase3_post() {
    int g = blockIdx.x * blockDim.x + threadIdx.x;
    int lane = g & 2047;
    int c = g >> 11;
    int b = lane >> 10, col = lane & 1023;
    float carry = g_scanC[g];
    float p = 1.f, acc = 0.f;
    int row0 = b * S_ + c * CHUNK_;
    const int hh = col >> 6;
    for (int t = 0; t < CHUNK_; t++) {
        int row = row0 + t;
        size_t b5 = (size_t)row * (5 * D_);
        float a, u;
        gdn_ua(b5, col, a, u);
        p *= a;
        acc += u / fmaxf(p, 1e-6f);
        float mem = p * (carry + acc);
        size_t idx = (size_t)row * D_ + col;
        float qh = g_proj[b5 + col] * g_rq[row * H_ + hh];
        float gate = 1.f / (1.f + expf(-g_proj[b5 + 4 * D_ + col]));
        float vv = g_proj[b5 + 2 * D_ + col];
        g_y[idx] = __float2bfloat16(gate * (qh * mem) + (1.f - gate) * vv);
    }
}

// ---- loss finalization ----
__global__ void loss_final() {
    __shared__ float mred[256], sred[256];
    int row = blockIdx.x;
    float2 v = g_ls[(size_t)row * 256 + threadIdx.x];
    mred[threadIdx.x] = v.x; sred[threadIdx.x] = v.y;
    __syncthreads();
    for (int o = 128; o > 0; o >>= 1) {
        if (threadIdx.x < o) {
            float m2 = mred[threadIdx.x + o], s2 = sred[threadIdx.x + o];
            float m1 = mred[threadIdx.x],     s1 = sred[threadIdx.x];
            float nm = fmaxf(m1, m2);
            mred[threadIdx.x] = nm;
            sred[threadIdx.x] = s1 * __expf(m1 - nm) + s2 * __expf(m2 - nm);
        }
        __syncthreads();
    }
    if (threadIdx.x == 0)
        g_rowloss[row] = -(g_tgtlog[row] - mred[0] - logf(sred[0]));
}

__global__ void loss_reduce_kernel(float* __restrict__ out) {
    __shared__ float red[256];
    float s = 0.f;
    for (int i = threadIdx.x; i < BS_; i += 256) s += g_rowloss[i];
    red[threadIdx.x] = s; __syncthreads();
    for (int o = 128; o > 0; o >>= 1) {
        if (threadIdx.x < o) red[threadIdx.x] += red[threadIdx.x + o];
        __syncthreads();
    }
    if (threadIdx.x == 0) out[0] = red[0] / (float)BS_;
}

// =====================================================================
// host orchestration
// =====================================================================
static void launch_gemm(const bf16* A, const bf16* W, void* C,
                        int M, int N, int K, float alpha, int mode,
                        const float* bias = nullptr, const int* tgt = nullptr) {
    dim3 grid(N / 128, M / 128);
    gemm_tc<<<grid, 256, GT_SMEM_BYTES>>>(A, W, C, M, N, K, alpha, mode, bias, tgt);
}
static void convert(const float* src, bf16* dst, size_t n) {
    int n4 = (int)(n / 4);
    f2bf_kernel<<<(n4 + 255) / 256, 256>>>(src, dst, n4);
}

extern "C" void kernel_launch(void* const* d_in, const int* in_sizes, int n_in,
                              void* d_out, int out_size) {
    const int*   input_ids   = (const int*)  d_in[0];
    const int*   target_ids  = (const int*)  d_in[1];
    const float* tok_emb     = (const float*)d_in[2];
    const float* lm_bias     = (const float*)d_in[3];
    const float* gdn_in_w    = (const float*)d_in[4];
    const float* gdn_out_w   = (const float*)d_in[5];
    const float* gdn_norm1   = (const float*)d_in[6];
    const float* gdn_norm2   = (const float*)d_in[7];
    const float* gdn_fc_w    = (const float*)d_in[8];
    const float* gdn_proj_w  = (const float*)d_in[9];
    const float* attn_qkv_w  = (const float*)d_in[10];
    const float* attn_proj_w = (const float*)d_in[11];
    const float* attn_norm1  = (const float*)d_in[12];
    const float* attn_norm2  = (const float*)d_in[13];
    const float* attn_fc_w   = (const float*)d_in[14];
    const float* attn_mlp_w  = (const float*)d_in[15];
    const float* final_norm  = (const float*)d_in[16];
    float* out = (float*)d_out;

    cudaFuncSetAttribute(gemm_tc, cudaFuncAttributeMaxDynamicSharedMemorySize,
                         GT_SMEM_BYTES);
    cudaFuncSetAttribute(flash_attn_tc, cudaFuncAttributeMaxDynamicSharedMemorySize,
                         FA_SMEM_BYTES);

    float *x, *proj;
    bf16 *xn, *y, *hid, *qkvb;
    bf16 *bw_in, *bw_out, *bw_fc, *bw_pj, *bw_qkv, *bw_apj, *bw_afc, *bw_ampj, *bw_emb;
    cudaGetSymbolAddress((void**)&x,      g_x);
    cudaGetSymbolAddress((void**)&xn,     g_xn);
    cudaGetSymbolAddress((void**)&proj,   g_proj);
    cudaGetSymbolAddress((void**)&y,      g_y);
    cudaGetSymbolAddress((void**)&hid,    g_hid);
    cudaGetSymbolAddress((void**)&qkvb,   g_qkv);
    cudaGetSymbolAddress((void**)&bw_in,   w_gdn_in);
    cudaGetSymbolAddress((void**)&bw_out,  w_gdn_out);
    cudaGetSymbolAddress((void**)&bw_fc,   w_gdn_fc);
    cudaGetSymbolAddress((void**)&bw_pj,   w_gdn_pj);
    cudaGetSymbolAddress((void**)&bw_qkv,  w_qkv);
    cudaGetSymbolAddress((void**)&bw_apj,  w_apj);
    cudaGetSymbolAddress((void**)&bw_afc,  w_afc);
    cudaGetSymbolAddress((void**)&bw_ampj, w_ampj);
    cudaGetSymbolAddress((void**)&bw_emb,  w_emb);

    convert(gdn_in_w,   bw_in,   (size_t)LG_ * 5 * D_ * D_);
    convert(gdn_out_w,  bw_out,  (size_t)LG_ * D_ * D_);
    convert(gdn_fc_w,   bw_fc,   (size_t)LG_ * HM_ * D_);
    convert(gdn_proj_w, bw_pj,   (size_t)LG_ * D_ * HM_);
    convert(attn_qkv_w, bw_qkv,  (size_t)3 * D_ * D_);
    convert(attn_proj_w, bw_apj, (size_t)D_ * D_);
    convert(attn_fc_w,  bw_afc,  (size_t)HM_ * D_);
    convert(attn_mlp_w, bw_ampj, (size_t)D_ * HM_);
    convert(tok_emb,    bw_emb,  (size_t)V_ * D_);

    embed_kernel<<<BS_, 256>>>(input_ids, tok_emb, x);

    for (int i = 0; i < LG_; i++) {
        float rsc = rsqrtf(2.0f * (i + 1));
        rmsnorm_kernel<<<BS_, 256>>>(x, gdn_norm1 + (size_t)i * D_, xn, 1e-6f);
        launch_gemm(xn, bw_in + (size_t)i * 5 * D_ * D_, proj, BS_, 5 * D_, D_, 1.f, 0);
        gdn_pre_q<<<BS_ * H_ / 8, 256>>>();
        scan_phase1<<<B_ * D_ * NCHUNK_ / 256, 256>>>();
        scan_phase2<<<B_ * D_ / 256, 256>>>();
        scan_phase3_post<<<B_ * D_ * NCHUNK_ / 256, 256>>>();
        launch_gemm(y, bw_out + (size_t)i * D_ * D_, x, BS_, D_, D_, rsc, 1);
        rmsnorm_kernel<<<BS_, 256>>>(x, gdn_norm2 + (size_t)i * D_, xn, 1e-6f);
        launch_gemm(xn, bw_fc + (size_t)i * HM_ * D_, hid, BS_, HM_, D_, 1.f, 2);
        launch_gemm(hid, bw_pj + (size_t)i * D_ * HM_, x, BS_, D_, HM_, rsc, 1);
    }

    float rsc = rsqrtf(2.0f * (LG_ + 1));
    rmsnorm_kernel<<<BS_, 256>>>(x, attn_norm1, xn, 1e-6f);
    launch_gemm(xn, bw_qkv, qkvb, BS_, 3 * D_, D_, 1.f, 3);
    {
        dim3 fgrid(S_ / FA_QTILE, H_, B_);
        flash_attn_tc<<<fgrid, 256, FA_SMEM_BYTES>>>();
    }
    launch_gemm(y, bw_apj, x, BS_, D_, D_, rsc, 1);
    rmsnorm_kernel<<<BS_, 256>>>(x, attn_norm2, xn, 1e-6f);
    launch_gemm(xn, bw_afc, hid, BS_, HM_, D_, 1.f, 2);
    launch_gemm(hid, bw_ampj, x, BS_, D_, HM_, rsc, 1);

    rmsnorm_kernel<<<BS_, 256>>>(x, final_norm, xn, 1e-6f);
    launch_gemm(xn, bw_emb, nullptr, BS_, V_, D_, 1.f, 4, lm_bias, target_ids);
    loss_final<<<BS_, 256>>>();
    loss_reduce_kernel<<<1, 256>>>(out);
}